// round 16
// baseline (speedup 1.0000x reference)
#include <cuda_runtime.h>
#include <cuda_fp16.h>
#include <cstdint>

#define NRES  384
#define NSEQ  256
#define NFEAT 64
#define NPROJ 32
#define NOUT  128
#define ICDIM (NRES*NPROJ)          // 12288
#define NPAIR (NRES*NRES)           // 147456
#define CD    (NPROJ*NPROJ)         // 1024
#define LN_EPS 1e-5f

// ------------------------- scratch (device globals) -------------------------
__device__ __half g_Lt[(size_t)ICDIM*NSEQ];   // [m=(i,c)][s]  K-major fp16
__device__ __half g_Rt[(size_t)ICDIM*NSEQ];   // [n=(j,d)][s]  K-major fp16
__device__ __half g_O [(size_t)NPAIR*CD];     // [(i,j)][(c,d)] fp16
__device__ __half g_Wob[NOUT*CD];             // Wo fp16 [o][cd]
__device__ float  g_normv[NPAIR];

// ------------------------- helpers -------------------------
__device__ __forceinline__ uint32_t smem_u32(const void* p){
    uint32_t a;
    asm("{ .reg .u64 t; cvta.to.shared.u64 t, %1; cvt.u32.u64 %0, t; }":"=r"(a):"l"(p));
    return a;
}
__device__ __forceinline__ void ldsm4(uint32_t& r0, uint32_t& r1, uint32_t& r2, uint32_t& r3, uint32_t a){
    asm volatile("ldmatrix.sync.aligned.m8n8.x4.shared.b16 {%0,%1,%2,%3}, [%4];"
        : "=r"(r0),"=r"(r1),"=r"(r2),"=r"(r3) : "r"(a));
}
// fp16-accum MMA: D packed as 2x f16x2
__device__ __forceinline__ void mma16816h(uint32_t* d, const uint32_t* a, uint32_t b0, uint32_t b1){
    asm volatile("mma.sync.aligned.m16n8k16.row.col.f16.f16.f16.f16 "
        "{%0,%1}, {%2,%3,%4,%5}, {%6,%7}, {%0,%1};"
        : "+r"(d[0]),"+r"(d[1])
        : "r"(a[0]),"r"(a[1]),"r"(a[2]),"r"(a[3]),"r"(b0),"r"(b1));
}
#define CP16(dst, src) asm volatile("cp.async.cg.shared.global [%0], [%1], 16;" \
    :: "r"(dst), "l"(src) : "memory")
#define CP_COMMIT() asm volatile("cp.async.commit_group;" ::: "memory")
#define CP_WAIT(n)  asm volatile("cp.async.wait_group %0;" :: "n"(n) : "memory")

// ---------------------------------------------------------------------------
// prep: LN (fp32) + projections (HFMA2) + mask; write transposed fp16 g_Lt/g_Rt.
// grid=384 (block per residue i), 256 threads (thread per s).
// ---------------------------------------------------------------------------
#define PREP_SMEM (2*4096 + 2*16384)   // WaH 4KB + WbH 4KB + sLb 16KB + sRb 16KB
__global__ void __launch_bounds__(256,2)
prep_kernel(const float* __restrict__ M, const float* __restrict__ mask,
            const float* __restrict__ gamma, const float* __restrict__ beta,
            const float* __restrict__ Wa, const float* __restrict__ ba,
            const float* __restrict__ Wb, const float* __restrict__ bb)
{
    extern __shared__ char psm[];
    __half2* sWaH = (__half2*)psm;              // [32 c][32 fpair]
    __half2* sWbH = sWaH + 1024;
    __half*  sLb  = (__half*)(psm + 8192);      // [32][256]
    __half*  sRb  = sLb + 8192;

    const int i = blockIdx.x;
    const int tid = threadIdx.x;
    for (int u = tid; u < NPROJ*NFEAT/2; u += 256){
        float2 wa = *(const float2*)(Wa + u*2);
        float2 wb = *(const float2*)(Wb + u*2);
        sWaH[u] = __floats2half2_rn(wa.x, wa.y);
        sWbH[u] = __floats2half2_rn(wb.x, wb.y);
    }

    const int s = tid;
    const float4* mr = (const float4*)(M + ((size_t)s*NRES + i)*NFEAT);
    float4 mn[16];
    float s1 = 0.f, s2 = 0.f;
    #pragma unroll
    for (int q = 0; q < 16; q++){
        float4 v = mr[q]; mn[q] = v;
        s1 += v.x + v.y + v.z + v.w;
        s2 += v.x*v.x + v.y*v.y + v.z*v.z + v.w*v.w;
    }
    float mu  = s1 * (1.f/64.f);
    float var = s2 * (1.f/64.f) - mu*mu;
    float inv = rsqrtf(var + LN_EPS);
    const float4* g4 = (const float4*)gamma;
    const float4* b4 = (const float4*)beta;
    __half2 mh[32];
    #pragma unroll
    for (int q = 0; q < 16; q++){
        float4 gg = g4[q], be = b4[q];
        float x = (mn[q].x - mu)*inv*gg.x + be.x;
        float y = (mn[q].y - mu)*inv*gg.y + be.y;
        float z = (mn[q].z - mu)*inv*gg.z + be.z;
        float w = (mn[q].w - mu)*inv*gg.w + be.w;
        mh[2*q]   = __floats2half2_rn(x, y);
        mh[2*q+1] = __floats2half2_rn(z, w);
    }
    const float msk = mask[(size_t)s*NRES + i];
    __syncthreads();

    #pragma unroll 4
    for (int c = 0; c < NPROJ; c++){
        __half2 a0 = __floats2half2_rn(0.f, 0.f), a1 = a0;
        __half2 b0 = a0, b1 = a0;
        const __half2* wa = sWaH + c*32;
        const __half2* wb = sWbH + c*32;
        #pragma unroll
        for (int q = 0; q < 16; q++){
            a0 = __hfma2(mh[2*q],   wa[2*q],   a0);
            a1 = __hfma2(mh[2*q+1], wa[2*q+1], a1);
            b0 = __hfma2(mh[2*q],   wb[2*q],   b0);
            b1 = __hfma2(mh[2*q+1], wb[2*q+1], b1);
        }
        float2 fa = __half22float2(__hadd2(a0, a1));
        float2 fb = __half22float2(__hadd2(b0, b1));
        float accA = ba[c] + fa.x + fa.y;
        float accB = bb[c] + fb.x + fb.y;
        sLb[c*256 + s] = __float2half(msk*accA);
        sRb[c*256 + s] = __float2half(msk*accB);
    }
    __syncthreads();

    for (int u = tid; u < NPROJ*128; u += 256){
        int c = u >> 7, sp = (u & 127) << 1;
        *(uint32_t*)(g_Lt + ((size_t)(i*NPROJ + c))*NSEQ + sp) = *(const uint32_t*)(sLb + c*256 + sp);
        *(uint32_t*)(g_Rt + ((size_t)(i*NPROJ + c))*NSEQ + sp) = *(const uint32_t*)(sRb + c*256 + sp);
    }
}

// ---------------------------------------------------------------------------
// norm + wconv fused: 32x32 tiles, grid (12,12)=144 CTAs. (R14-verified)
// ---------------------------------------------------------------------------
__global__ void __launch_bounds__(256,1)
norm_kernel(const float* __restrict__ mask, const float* __restrict__ Wo)
{
    __shared__ float sa [128*32];
    __shared__ float sbv[128*32];
    const int tid = threadIdx.x;
    const int bi = blockIdx.y, bj = blockIdx.x;
    const int tx = tid & 15, ty = tid >> 4;

    {
        int base = ((bi*12 + bj)*256 + tid) * 4;
        if (base < NOUT*CD){
            float4 wv = *(const float4*)(Wo + base);
            __half2 h0 = __floats2half2_rn(wv.x, wv.y);
            __half2 h1 = __floats2half2_rn(wv.z, wv.w);
            uint2 pk = make_uint2(*(uint32_t*)&h0, *(uint32_t*)&h1);
            *(uint2*)(g_Wob + base) = pk;
        }
    }

    float acc[2][2] = {{0.f,0.f},{0.f,0.f}};

    #pragma unroll 1
    for (int sc = 0; sc < 2; sc++){
        __syncthreads();
        #pragma unroll
        for (int p = 0; p < 16; p++){
            int s = p*8 + (tid >> 5);
            int c = tid & 31;
            sa [s*32 + c] = mask[(size_t)(sc*128 + s)*NRES + bi*32 + c];
            sbv[s*32 + c] = mask[(size_t)(sc*128 + s)*NRES + bj*32 + c];
        }
        __syncthreads();
        #pragma unroll 8
        for (int s = 0; s < 128; s++){
            float2 av = *(const float2*)(sa  + s*32 + ty*2);
            float2 bv = *(const float2*)(sbv + s*32 + tx*2);
            acc[0][0] += av.x*bv.x; acc[0][1] += av.x*bv.y;
            acc[1][0] += av.y*bv.x; acc[1][1] += av.y*bv.y;
        }
    }

    #pragma unroll
    for (int a = 0; a < 2; a++){
        int i = bi*32 + ty*2 + a;
        #pragma unroll
        for (int b = 0; b < 2; b++){
            int j = bj*32 + tx*2 + b;
            g_normv[(size_t)i*NRES + j] = acc[a][b];
        }
    }
}

// ---------------------------------------------------------------------------
// gemm1: O[256x128] = Lt[it*256..] @ Rt[jt*128..]^T, K=256, fp16 accum.
// 256 threads, 8 warps (4m x 2n of 64x64). 2-stage cp.async (96KB), occ 2
// => 16 warps/SM. Single-buffered fragments (<=128 regs).
// Smem-staged coalesced epilogue.
// ---------------------------------------------------------------------------
#define G1_STAGE 49152               // A 32KB + B 16KB
#define G1_SMEM (2*G1_STAGE)         // 98304
#define OSTR 136                     // fp16 stride of epilogue tile
__global__ void __launch_bounds__(256,2) gemm1_kernel()
{
    extern __shared__ char sm1[];
    const int tid = threadIdx.x, lane = tid & 31, w = tid >> 5;
    const int it = blockIdx.y, jt = blockIdx.x;
    const int wr = w >> 1, wc = w & 1;          // wr 0..3, wc 0..1
    const int m0 = wr*64, n0 = wc*64;
    const int lo7 = lane & 7, hi = lane >> 4, l15 = lane & 15;

    const uint32_t sb = smem_u32(sm1);
    const int brow = tid >> 1;                  // 0..127 (B row)
    const int bq0  = (tid & 1) << 2;            // 0 or 4

    uint32_t rA[4], rB[4];
    #pragma unroll
    for (int mt = 0; mt < 4; mt++) rA[mt] = (m0 + mt*16 + l15)*128;
    #pragma unroll
    for (int nb = 0; nb < 4; nb++) rB[nb] = 32768 + (n0 + nb*16 + l15)*128;

    // A: 256 rows x 128B (32KB); B: 128 rows x 128B (16KB) at +32768
    #define G1_LOAD(kc, s) do {                                               \
        _Pragma("unroll")                                                     \
        for (int q = 0; q < 8; q++){                                          \
            int cp = q ^ (tid & 7);                                           \
            uint32_t da = sb + (s)*G1_STAGE + tid*128 + cp*16;                \
            CP16(da, (const void*)(g_Lt + ((size_t)(it*256 + tid))*NSEQ + (kc)*64 + q*8)); \
        }                                                                     \
        _Pragma("unroll")                                                     \
        for (int qq = 0; qq < 4; qq++){                                       \
            int q = bq0 + qq;                                                 \
            int cp = q ^ (brow & 7);                                          \
            uint32_t db = sb + (s)*G1_STAGE + 32768 + brow*128 + cp*16;       \
            CP16(db, (const void*)(g_Rt + ((size_t)(jt*128 + brow))*NSEQ + (kc)*64 + q*8)); \
        }                                                                     \
    } while(0)

    uint32_t hacc[4][8][2];
    #pragma unroll
    for (int a = 0; a < 4; a++)
        #pragma unroll
        for (int b = 0; b < 8; b++){ hacc[a][b][0] = 0u; hacc[a][b][1] = 0u; }

    uint32_t af[4][4], bf[4][4];

    G1_LOAD(0, 0); CP_COMMIT();

    #pragma unroll 1
    for (int kc = 0; kc < 4; kc++){
        if (kc + 1 < 4){ G1_LOAD(kc+1, (kc+1)&1); CP_COMMIT(); CP_WAIT(1); }
        else { CP_WAIT(0); }
        __syncthreads();
        const uint32_t sS = sb + (kc&1)*G1_STAGE;
        #pragma unroll
        for (int ks = 0; ks < 4; ks++){
            const int ch = ((ks*2 + hi) ^ lo7) << 4;
            #pragma unroll
            for (int mt = 0; mt < 4; mt++)
                ldsm4(af[mt][0],af[mt][1],af[mt][2],af[mt][3], sS + rA[mt] + ch);
            #pragma unroll
            for (int nb = 0; nb < 4; nb++)
                ldsm4(bf[nb][0],bf[nb][1],bf[nb][2],bf[nb][3], sS + rB[nb] + ch);
            #pragma unroll
            for (int mt = 0; mt < 4; mt++)
                #pragma unroll
                for (int nb = 0; nb < 4; nb++){
                    mma16816h(hacc[mt][nb*2],   af[mt], bf[nb][0], bf[nb][2]);
                    mma16816h(hacc[mt][nb*2+1], af[mt], bf[nb][1], bf[nb][3]);
                }
        }
        __syncthreads();
    }

    // -------- epilogue: stage fp16 tile [256][OSTR] in smem, coalesced out --
    __half* Ot = (__half*)sm1;       // 256*136*2 = 69632 <= 96KB
    const int rbase = lane >> 2, cpair = (lane & 3)*2;
    #pragma unroll
    for (int mt = 0; mt < 4; mt++){
        int r0 = m0 + mt*16 + rbase;
        int r1 = r0 + 8;
        #pragma unroll
        for (int nt = 0; nt < 8; nt++){
            int col = n0 + nt*8 + cpair;
            *(uint32_t*)(Ot + r0*OSTR + col) = hacc[mt][nt][0];
            *(uint32_t*)(Ot + r1*OSTR + col) = hacc[mt][nt][1];
        }
    }
    __syncthreads();
    // 32 pairs, each 1024 fp16 contiguous in g_O; 256 threads x 8B
    #pragma unroll 1
    for (int p = 0; p < 32; p++){
        int ri = p >> 2, cj = p & 3;               // ri 0..7, cj 0..3
        size_t gbase = (((size_t)(it*8 + ri)*NRES + jt*4 + cj) << 10);
        int c  = tid >> 3;            // 0..31
        int d4 = (tid & 7) * 4;       // 0..28
        uint2 v = *(const uint2*)(Ot + (ri*32 + c)*OSTR + cj*32 + d4);
        *(uint2*)(g_O + gbase + c*32 + d4) = v;
    }
}

// ---------------------------------------------------------------------------
// gemm2: Z[m,o] = sum_k O[m,k]*Wob[o,k], m-tile 128, o=128, K=1024, fp16 acc.
// 128 threads, 4 warps, 64x64 warp tiles, 2-stage cp.async (64KB), occ 3.
// Direct fused epilogue.  (R9-verified configuration)
// ---------------------------------------------------------------------------
#define G2_SMEM (2*32768)
__global__ void __launch_bounds__(128,3)
gemm2_kernel(const float* __restrict__ Zraw, const float* __restrict__ bo,
             float* __restrict__ out)
{
    extern __shared__ char sm2[];
    __shared__ float sbo[NOUT];
    const int tid = threadIdx.x, lane = tid & 31, w = tid >> 5;
    const int m0 = blockIdx.x * 128;
    const int wr = w >> 1, wc = w & 1;
    const int mw0 = wr*64, o0 = wc*64;
    const int lo7 = lane & 7, hi = lane >> 4, l15 = lane & 15;

    const uint32_t sb = smem_u32(sm2);
    if (tid < NOUT) sbo[tid] = bo[tid];

    const int lrb = tid >> 3;
    const int lc  = tid & 7;

    uint32_t rA[4], rB[4];
    #pragma unroll
    for (int mt = 0; mt < 4; mt++) rA[mt] = (mw0 + mt*16 + l15)*128;
    #pragma unroll
    for (int nb = 0; nb < 4; nb++) rB[nb] = (o0 + nb*16 + l15)*128;

    #define G2_LOAD(kc, s) do {                                               \
        _Pragma("unroll")                                                     \
        for (int q = 0; q < 8; q++){                                          \
            int row = q*16 + lrb;                                             \
            int cp = lc ^ (row & 7);                                          \
            uint32_t da = sb + (s)*32768 + row*128 + cp*16;                   \
            CP16(da,         (const void*)(g_O   + (size_t)(m0 + row)*CD + (kc)*64 + lc*8)); \
            CP16(da + 16384, (const void*)(g_Wob + (size_t)row*CD        + (kc)*64 + lc*8)); \
        }                                                                     \
    } while(0)

    uint32_t hacc[4][8][2];
    #pragma unroll
    for (int a = 0; a < 4; a++)
        #pragma unroll
        for (int b = 0; b < 8; b++){ hacc[a][b][0] = 0u; hacc[a][b][1] = 0u; }

    uint32_t af[2][4][4], bf[2][4][4];

    #define G2_LDFRAG(buf, ch) do {                                           \
        _Pragma("unroll")                                                     \
        for (int mt = 0; mt < 4; mt++)                                        \
            ldsm4(af[buf][mt][0],af[buf][mt][1],af[buf][mt][2],af[buf][mt][3], sA + rA[mt] + (ch)); \
        _Pragma("unroll")                                                     \
        for (int nb = 0; nb < 4; nb++)                                        \
            ldsm4(bf[buf][nb][0],bf[buf][nb][1],bf[buf][nb][2],bf[buf][nb][3], sB + rB[nb] + (ch)); \
    } while(0)

    #define G2_MMA(buf) do {                                                  \
        _Pragma("unroll")                                                     \
        for (int mt = 0; mt < 4; mt++)                                        \
            _Pragma("unroll")                                                 \
            for (int nb = 0; nb < 4; nb++){                                   \
                mma16816h(hacc[mt][nb*2],   af[buf][mt], bf[buf][nb][0], bf[buf][nb][2]); \
                mma16816h(hacc[mt][nb*2+1], af[buf][mt], bf[buf][nb][1], bf[buf][nb][3]); \
            }                                                                 \
    } while(0)

    G2_LOAD(0, 0); CP_COMMIT();

    #pragma unroll 1
    for (int kc = 0; kc < 16; kc++){
        if (kc + 1 < 16){ G2_LOAD(kc+1, (kc+1)&1); CP_COMMIT(); CP_WAIT(1); }
        else { CP_WAIT(0); }
        __syncthreads();
        const uint32_t sA = sb + (kc&1)*32768;
        const uint32_t sB = sA + 16384;
        G2_LDFRAG(0, (hi ^ lo7) << 4);
        #pragma unroll
        for (int ks = 0; ks < 4; ks++){
            if (ks < 3){
                int chn = (((ks+1)*2 + hi) ^ lo7) << 4;
                G2_LDFRAG((ks+1)&1, chn);
            }
            G2_MMA(ks&1);
        }
        __syncthreads();
    }

    // direct fused epilogue: (z+bo)*invn + Zraw  (unpack half2 accumulators)
    const int rbase = lane >> 2, cpair = (lane & 3)*2;
    #pragma unroll
    for (int mt = 0; mt < 4; mt++){
        int mA = m0 + mw0 + mt*16 + rbase;
        int mB = mA + 8;
        float invA = 1.0f / (0.001f + g_normv[mA]);
        float invB = 1.0f / (0.001f + g_normv[mB]);
        #pragma unroll
        for (int nt = 0; nt < 8; nt++){
            int o = o0 + nt*8 + cpair;
            float b0 = sbo[o], b1 = sbo[o+1];
            float2 vA = __half22float2(*(__half2*)&hacc[mt][nt][0]);
            float2 vB = __half22float2(*(__half2*)&hacc[mt][nt][1]);
            float2 zA = *(const float2*)(Zraw + (size_t)mA*NOUT + o);
            float2 zB = *(const float2*)(Zraw + (size_t)mB*NOUT + o);
            float2 rrA, rrB;
            rrA.x = (vA.x + b0)*invA + zA.x;
            rrA.y = (vA.y + b1)*invA + zA.y;
            rrB.x = (vB.x + b0)*invB + zB.x;
            rrB.y = (vB.y + b1)*invB + zB.y;
            *(float2*)(out + (size_t)mA*NOUT + o) = rrA;
            *(float2*)(out + (size_t)mB*NOUT + o) = rrB;
        }
    }
}

// ---------------------------------------------------------------------------
extern "C" void kernel_launch(void* const* d_in, const int* in_sizes, int n_in,
                              void* d_out, int out_size)
{
    const float* M     = (const float*)d_in[0];
    const float* mask  = (const float*)d_in[1];
    const float* Zraw  = (const float*)d_in[2];
    const float* gamma = (const float*)d_in[3];
    const float* beta  = (const float*)d_in[4];
    const float* Wa    = (const float*)d_in[5];
    const float* ba    = (const float*)d_in[6];
    const float* Wb    = (const float*)d_in[7];
    const float* bb    = (const float*)d_in[8];
    const float* Wo    = (const float*)d_in[9];
    const float* bo    = (const float*)d_in[10];
    float* out = (float*)d_out;

    cudaFuncSetAttribute(prep_kernel,  cudaFuncAttributeMaxDynamicSharedMemorySize, PREP_SMEM);
    cudaFuncSetAttribute(gemm1_kernel, cudaFuncAttributeMaxDynamicSharedMemorySize, G1_SMEM);
    cudaFuncSetAttribute(gemm2_kernel, cudaFuncAttributeMaxDynamicSharedMemorySize, G2_SMEM);

    prep_kernel<<<NRES, 256, PREP_SMEM>>>(M, mask, gamma, beta, Wa, ba, Wb, bb);
    norm_kernel<<<dim3(12,12), 256>>>(mask, Wo);
    gemm1_kernel<<<dim3(96, 48), 256, G1_SMEM>>>();
    gemm2_kernel<<<NPAIR/128, 128, G2_SMEM>>>(Zraw, bo, out);
}

// round 17
// speedup vs baseline: 1.4289x; 1.4289x over previous
#include <cuda_runtime.h>
#include <cuda_fp16.h>
#include <cstdint>

#define NRES  384
#define NSEQ  256
#define NFEAT 64
#define NPROJ 32
#define NOUT  128
#define ICDIM (NRES*NPROJ)          // 12288
#define NPAIR (NRES*NRES)           // 147456
#define CD    (NPROJ*NPROJ)         // 1024
#define LN_EPS 1e-5f

// ------------------------- scratch (device globals) -------------------------
__device__ __half g_Lt[(size_t)ICDIM*NSEQ];   // [m=(i,c)][s]  K-major fp16
__device__ __half g_Rt[(size_t)ICDIM*NSEQ];   // [n=(j,d)][s]  K-major fp16
__device__ __half g_O [(size_t)NPAIR*CD];     // [(i,j)][(c,d)] fp16
__device__ __half g_Wob[NOUT*CD];             // Wo fp16 [o][cd]
__device__ float  g_normv[NPAIR];

// ------------------------- helpers -------------------------
__device__ __forceinline__ uint32_t smem_u32(const void* p){
    uint32_t a;
    asm("{ .reg .u64 t; cvta.to.shared.u64 t, %1; cvt.u32.u64 %0, t; }":"=r"(a):"l"(p));
    return a;
}
__device__ __forceinline__ void ldsm4(uint32_t& r0, uint32_t& r1, uint32_t& r2, uint32_t& r3, uint32_t a){
    asm volatile("ldmatrix.sync.aligned.m8n8.x4.shared.b16 {%0,%1,%2,%3}, [%4];"
        : "=r"(r0),"=r"(r1),"=r"(r2),"=r"(r3) : "r"(a));
}
// fp16-accum MMA: D packed as 2x f16x2
__device__ __forceinline__ void mma16816h(uint32_t* d, const uint32_t* a, uint32_t b0, uint32_t b1){
    asm volatile("mma.sync.aligned.m16n8k16.row.col.f16.f16.f16.f16 "
        "{%0,%1}, {%2,%3,%4,%5}, {%6,%7}, {%0,%1};"
        : "+r"(d[0]),"+r"(d[1])
        : "r"(a[0]),"r"(a[1]),"r"(a[2]),"r"(a[3]),"r"(b0),"r"(b1));
}
#define CP16(dst, src) asm volatile("cp.async.cg.shared.global [%0], [%1], 16;" \
    :: "r"(dst), "l"(src) : "memory")
#define CP_COMMIT() asm volatile("cp.async.commit_group;" ::: "memory")
#define CP_WAIT(n)  asm volatile("cp.async.wait_group %0;" :: "n"(n) : "memory")

// ---------------------------------------------------------------------------
// prep: LN (fp32) + projections (HFMA2) + mask; write transposed fp16 g_Lt/g_Rt.
// grid=384 (block per residue i), 256 threads (thread per s).
// ---------------------------------------------------------------------------
#define PREP_SMEM (2*4096 + 2*16384)   // WaH 4KB + WbH 4KB + sLb 16KB + sRb 16KB
__global__ void __launch_bounds__(256,2)
prep_kernel(const float* __restrict__ M, const float* __restrict__ mask,
            const float* __restrict__ gamma, const float* __restrict__ beta,
            const float* __restrict__ Wa, const float* __restrict__ ba,
            const float* __restrict__ Wb, const float* __restrict__ bb)
{
    extern __shared__ char psm[];
    __half2* sWaH = (__half2*)psm;              // [32 c][32 fpair]
    __half2* sWbH = sWaH + 1024;
    __half*  sLb  = (__half*)(psm + 8192);      // [32][256]
    __half*  sRb  = sLb + 8192;

    const int i = blockIdx.x;
    const int tid = threadIdx.x;
    for (int u = tid; u < NPROJ*NFEAT/2; u += 256){
        float2 wa = *(const float2*)(Wa + u*2);
        float2 wb = *(const float2*)(Wb + u*2);
        sWaH[u] = __floats2half2_rn(wa.x, wa.y);
        sWbH[u] = __floats2half2_rn(wb.x, wb.y);
    }

    const int s = tid;
    const float4* mr = (const float4*)(M + ((size_t)s*NRES + i)*NFEAT);
    float4 mn[16];
    float s1 = 0.f, s2 = 0.f;
    #pragma unroll
    for (int q = 0; q < 16; q++){
        float4 v = mr[q]; mn[q] = v;
        s1 += v.x + v.y + v.z + v.w;
        s2 += v.x*v.x + v.y*v.y + v.z*v.z + v.w*v.w;
    }
    float mu  = s1 * (1.f/64.f);
    float var = s2 * (1.f/64.f) - mu*mu;
    float inv = rsqrtf(var + LN_EPS);
    const float4* g4 = (const float4*)gamma;
    const float4* b4 = (const float4*)beta;
    __half2 mh[32];
    #pragma unroll
    for (int q = 0; q < 16; q++){
        float4 gg = g4[q], be = b4[q];
        float x = (mn[q].x - mu)*inv*gg.x + be.x;
        float y = (mn[q].y - mu)*inv*gg.y + be.y;
        float z = (mn[q].z - mu)*inv*gg.z + be.z;
        float w = (mn[q].w - mu)*inv*gg.w + be.w;
        mh[2*q]   = __floats2half2_rn(x, y);
        mh[2*q+1] = __floats2half2_rn(z, w);
    }
    const float msk = mask[(size_t)s*NRES + i];
    __syncthreads();

    #pragma unroll 4
    for (int c = 0; c < NPROJ; c++){
        __half2 a0 = __floats2half2_rn(0.f, 0.f), a1 = a0;
        __half2 b0 = a0, b1 = a0;
        const __half2* wa = sWaH + c*32;
        const __half2* wb = sWbH + c*32;
        #pragma unroll
        for (int q = 0; q < 16; q++){
            a0 = __hfma2(mh[2*q],   wa[2*q],   a0);
            a1 = __hfma2(mh[2*q+1], wa[2*q+1], a1);
            b0 = __hfma2(mh[2*q],   wb[2*q],   b0);
            b1 = __hfma2(mh[2*q+1], wb[2*q+1], b1);
        }
        float2 fa = __half22float2(__hadd2(a0, a1));
        float2 fb = __half22float2(__hadd2(b0, b1));
        float accA = ba[c] + fa.x + fa.y;
        float accB = bb[c] + fb.x + fb.y;
        sLb[c*256 + s] = __float2half(msk*accA);
        sRb[c*256 + s] = __float2half(msk*accB);
    }
    __syncthreads();

    for (int u = tid; u < NPROJ*128; u += 256){
        int c = u >> 7, sp = (u & 127) << 1;
        *(uint32_t*)(g_Lt + ((size_t)(i*NPROJ + c))*NSEQ + sp) = *(const uint32_t*)(sLb + c*256 + sp);
        *(uint32_t*)(g_Rt + ((size_t)(i*NPROJ + c))*NSEQ + sp) = *(const uint32_t*)(sRb + c*256 + sp);
    }
}

// ---------------------------------------------------------------------------
// norm + wconv fused: 32x32 tiles, grid (12,12)=144 CTAs. (R14-verified)
// ---------------------------------------------------------------------------
__global__ void __launch_bounds__(256,1)
norm_kernel(const float* __restrict__ mask, const float* __restrict__ Wo)
{
    __shared__ float sa [128*32];
    __shared__ float sbv[128*32];
    const int tid = threadIdx.x;
    const int bi = blockIdx.y, bj = blockIdx.x;
    const int tx = tid & 15, ty = tid >> 4;

    {
        int base = ((bi*12 + bj)*256 + tid) * 4;
        if (base < NOUT*CD){
            float4 wv = *(const float4*)(Wo + base);
            __half2 h0 = __floats2half2_rn(wv.x, wv.y);
            __half2 h1 = __floats2half2_rn(wv.z, wv.w);
            uint2 pk = make_uint2(*(uint32_t*)&h0, *(uint32_t*)&h1);
            *(uint2*)(g_Wob + base) = pk;
        }
    }

    float acc[2][2] = {{0.f,0.f},{0.f,0.f}};

    #pragma unroll 1
    for (int sc = 0; sc < 2; sc++){
        __syncthreads();
        #pragma unroll
        for (int p = 0; p < 16; p++){
            int s = p*8 + (tid >> 5);
            int c = tid & 31;
            sa [s*32 + c] = mask[(size_t)(sc*128 + s)*NRES + bi*32 + c];
            sbv[s*32 + c] = mask[(size_t)(sc*128 + s)*NRES + bj*32 + c];
        }
        __syncthreads();
        #pragma unroll 8
        for (int s = 0; s < 128; s++){
            float2 av = *(const float2*)(sa  + s*32 + ty*2);
            float2 bv = *(const float2*)(sbv + s*32 + tx*2);
            acc[0][0] += av.x*bv.x; acc[0][1] += av.x*bv.y;
            acc[1][0] += av.y*bv.x; acc[1][1] += av.y*bv.y;
        }
    }

    #pragma unroll
    for (int a = 0; a < 2; a++){
        int i = bi*32 + ty*2 + a;
        #pragma unroll
        for (int b = 0; b < 2; b++){
            int j = bj*32 + tx*2 + b;
            g_normv[(size_t)i*NRES + j] = acc[a][b];
        }
    }
}

// ---------------------------------------------------------------------------
// gemm1: O[128x128] = Lt[it*128..] @ Rt[jt*128..]^T, K=256, fp16 accum.
// 128 threads, 4 warps, 64x64 warp tiles. 2-stage cp.async ring (64KB), occ 3.
// Smem-staged coalesced epilogue.  (R14-verified configuration)
// ---------------------------------------------------------------------------
#define G1_SMEM (2*32768)
#define OSTR 136                     // fp16 stride of epilogue tile
__global__ void __launch_bounds__(128,3) gemm1_kernel()
{
    extern __shared__ char sm1[];
    const int tid = threadIdx.x, lane = tid & 31, w = tid >> 5;
    const int it = blockIdx.y, jt = blockIdx.x;
    const int wr = w >> 1, wc = w & 1;
    const int m0 = wr*64, n0 = wc*64;
    const int lo7 = lane & 7, hi = lane >> 4, l15 = lane & 15;

    const uint32_t sb = smem_u32(sm1);
    const int lrb = tid >> 3;        // 0..15
    const int lc  = tid & 7;         // 16B-unit col 0..7

    uint32_t rA[4], rB[4];
    #pragma unroll
    for (int mt = 0; mt < 4; mt++) rA[mt] = (m0 + mt*16 + l15)*128;
    #pragma unroll
    for (int nb = 0; nb < 4; nb++) rB[nb] = (n0 + nb*16 + l15)*128;

    #define G1_LOAD(kc, s) do {                                               \
        _Pragma("unroll")                                                     \
        for (int q = 0; q < 8; q++){                                          \
            int row = q*16 + lrb;                                             \
            int cp = lc ^ (row & 7);                                          \
            uint32_t da = sb + (s)*32768 + row*128 + cp*16;                   \
            CP16(da,         (const void*)(g_Lt + ((size_t)(it*128 + row))*NSEQ + (kc)*64 + lc*8)); \
            CP16(da + 16384, (const void*)(g_Rt + ((size_t)(jt*128 + row))*NSEQ + (kc)*64 + lc*8)); \
        }                                                                     \
    } while(0)

    uint32_t hacc[4][8][2];
    #pragma unroll
    for (int a = 0; a < 4; a++)
        #pragma unroll
        for (int b = 0; b < 8; b++){ hacc[a][b][0] = 0u; hacc[a][b][1] = 0u; }

    uint32_t af[2][4][4], bf[2][4][4];

    #define G1_LDFRAG(buf, ch) do {                                           \
        _Pragma("unroll")                                                     \
        for (int mt = 0; mt < 4; mt++)                                        \
            ldsm4(af[buf][mt][0],af[buf][mt][1],af[buf][mt][2],af[buf][mt][3], sA + rA[mt] + (ch)); \
        _Pragma("unroll")                                                     \
        for (int nb = 0; nb < 4; nb++)                                        \
            ldsm4(bf[buf][nb][0],bf[buf][nb][1],bf[buf][nb][2],bf[buf][nb][3], sB + rB[nb] + (ch)); \
    } while(0)

    #define G1_MMA(buf) do {                                                  \
        _Pragma("unroll")                                                     \
        for (int mt = 0; mt < 4; mt++)                                        \
            _Pragma("unroll")                                                 \
            for (int nb = 0; nb < 4; nb++){                                   \
                mma16816h(hacc[mt][nb*2],   af[buf][mt], bf[buf][nb][0], bf[buf][nb][2]); \
                mma16816h(hacc[mt][nb*2+1], af[buf][mt], bf[buf][nb][1], bf[buf][nb][3]); \
            }                                                                 \
    } while(0)

    G1_LOAD(0, 0); CP_COMMIT();

    #pragma unroll 1
    for (int kc = 0; kc < 4; kc++){
        if (kc + 1 < 4){ G1_LOAD(kc+1, (kc+1)&1); CP_COMMIT(); CP_WAIT(1); }
        else { CP_WAIT(0); }
        __syncthreads();
        const uint32_t sA = sb + (kc&1)*32768;
        const uint32_t sB = sA + 16384;
        G1_LDFRAG(0, (hi ^ lo7) << 4);
        #pragma unroll
        for (int ks = 0; ks < 4; ks++){
            if (ks < 3){
                int chn = (((ks+1)*2 + hi) ^ lo7) << 4;
                G1_LDFRAG((ks+1)&1, chn);
            }
            G1_MMA(ks&1);
        }
        __syncthreads();
    }

    // -------- epilogue: stage fp16 tile in smem, then coalesced stores -----
    __half* Ot = (__half*)sm1;       // [128][OSTR]
    const int rbase = lane >> 2, cpair = (lane & 3)*2;
    #pragma unroll
    for (int mt = 0; mt < 4; mt++){
        int r0 = m0 + mt*16 + rbase;
        int r1 = r0 + 8;
        #pragma unroll
        for (int nt = 0; nt < 8; nt++){
            int col = n0 + nt*8 + cpair;
            *(uint32_t*)(Ot + r0*OSTR + col) = hacc[mt][nt][0];
            *(uint32_t*)(Ot + r1*OSTR + col) = hacc[mt][nt][1];
        }
    }
    __syncthreads();
    // 16 pairs, each 1024 fp16 contiguous in g_O
    #pragma unroll 1
    for (int p = 0; p < 16; p++){
        int ri = p >> 2, cj = p & 3;
        size_t gbase = (((size_t)(it*4 + ri)*NRES + jt*4 + cj) << 10);
        int c  = tid >> 2;            // 0..31
        int d8 = (tid & 3) * 8;       // 0,8,16,24
        uint4 v = *(const uint4*)(Ot + (ri*32 + c)*OSTR + cj*32 + d8);
        *(uint4*)(g_O + gbase + c*32 + d8) = v;
    }
}

// ---------------------------------------------------------------------------
// gemm2: Z[m,o] = sum_k O[m,k]*Wob[o,k], m-tile 128, o=128, K=1024, fp16 acc.
// 128 threads, 4 warps, 64x64 warp tiles, 2-stage cp.async (64KB), occ 3.
// Direct fused epilogue.  (R14-verified configuration)
// ---------------------------------------------------------------------------
#define G2_SMEM (2*32768)
__global__ void __launch_bounds__(128,3)
gemm2_kernel(const float* __restrict__ Zraw, const float* __restrict__ bo,
             float* __restrict__ out)
{
    extern __shared__ char sm2[];
    __shared__ float sbo[NOUT];
    const int tid = threadIdx.x, lane = tid & 31, w = tid >> 5;
    const int m0 = blockIdx.x * 128;
    const int wr = w >> 1, wc = w & 1;
    const int mw0 = wr*64, o0 = wc*64;
    const int lo7 = lane & 7, hi = lane >> 4, l15 = lane & 15;

    const uint32_t sb = smem_u32(sm2);
    if (tid < NOUT) sbo[tid] = bo[tid];

    const int lrb = tid >> 3;
    const int lc  = tid & 7;

    uint32_t rA[4], rB[4];
    #pragma unroll
    for (int mt = 0; mt < 4; mt++) rA[mt] = (mw0 + mt*16 + l15)*128;
    #pragma unroll
    for (int nb = 0; nb < 4; nb++) rB[nb] = (o0 + nb*16 + l15)*128;

    #define G2_LOAD(kc, s) do {                                               \
        _Pragma("unroll")                                                     \
        for (int q = 0; q < 8; q++){                                          \
            int row = q*16 + lrb;                                             \
            int cp = lc ^ (row & 7);                                          \
            uint32_t da = sb + (s)*32768 + row*128 + cp*16;                   \
            CP16(da,         (const void*)(g_O   + (size_t)(m0 + row)*CD + (kc)*64 + lc*8)); \
            CP16(da + 16384, (const void*)(g_Wob + (size_t)row*CD        + (kc)*64 + lc*8)); \
        }                                                                     \
    } while(0)

    uint32_t hacc[4][8][2];
    #pragma unroll
    for (int a = 0; a < 4; a++)
        #pragma unroll
        for (int b = 0; b < 8; b++){ hacc[a][b][0] = 0u; hacc[a][b][1] = 0u; }

    uint32_t af[2][4][4], bf[2][4][4];

    #define G2_LDFRAG(buf, ch) do {                                           \
        _Pragma("unroll")                                                     \
        for (int mt = 0; mt < 4; mt++)                                        \
            ldsm4(af[buf][mt][0],af[buf][mt][1],af[buf][mt][2],af[buf][mt][3], sA + rA[mt] + (ch)); \
        _Pragma("unroll")                                                     \
        for (int nb = 0; nb < 4; nb++)                                        \
            ldsm4(bf[buf][nb][0],bf[buf][nb][1],bf[buf][nb][2],bf[buf][nb][3], sB + rB[nb] + (ch)); \
    } while(0)

    #define G2_MMA(buf) do {                                                  \
        _Pragma("unroll")                                                     \
        for (int mt = 0; mt < 4; mt++)                                        \
            _Pragma("unroll")                                                 \
            for (int nb = 0; nb < 4; nb++){                                   \
                mma16816h(hacc[mt][nb*2],   af[buf][mt], bf[buf][nb][0], bf[buf][nb][2]); \
                mma16816h(hacc[mt][nb*2+1], af[buf][mt], bf[buf][nb][1], bf[buf][nb][3]); \
            }                                                                 \
    } while(0)

    G2_LOAD(0, 0); CP_COMMIT();

    #pragma unroll 1
    for (int kc = 0; kc < 16; kc++){
        if (kc + 1 < 16){ G2_LOAD(kc+1, (kc+1)&1); CP_COMMIT(); CP_WAIT(1); }
        else { CP_WAIT(0); }
        __syncthreads();
        const uint32_t sA = sb + (kc&1)*32768;
        const uint32_t sB = sA + 16384;
        G2_LDFRAG(0, (hi ^ lo7) << 4);
        #pragma unroll
        for (int ks = 0; ks < 4; ks++){
            if (ks < 3){
                int chn = (((ks+1)*2 + hi) ^ lo7) << 4;
                G2_LDFRAG((ks+1)&1, chn);
            }
            G2_MMA(ks&1);
        }
        __syncthreads();
    }

    // direct fused epilogue: (z+bo)*invn + Zraw  (unpack half2 accumulators)
    const int rbase = lane >> 2, cpair = (lane & 3)*2;
    #pragma unroll
    for (int mt = 0; mt < 4; mt++){
        int mA = m0 + mw0 + mt*16 + rbase;
        int mB = mA + 8;
        float invA = 1.0f / (0.001f + g_normv[mA]);
        float invB = 1.0f / (0.001f + g_normv[mB]);
        #pragma unroll
        for (int nt = 0; nt < 8; nt++){
            int o = o0 + nt*8 + cpair;
            float b0 = sbo[o], b1 = sbo[o+1];
            float2 vA = __half22float2(*(__half2*)&hacc[mt][nt][0]);
            float2 vB = __half22float2(*(__half2*)&hacc[mt][nt][1]);
            float2 zA = *(const float2*)(Zraw + (size_t)mA*NOUT + o);
            float2 zB = *(const float2*)(Zraw + (size_t)mB*NOUT + o);
            float2 rrA, rrB;
            rrA.x = (vA.x + b0)*invA + zA.x;
            rrA.y = (vA.y + b1)*invA + zA.y;
            rrB.x = (vB.x + b0)*invB + zB.x;
            rrB.y = (vB.y + b1)*invB + zB.y;
            *(float2*)(out + (size_t)mA*NOUT + o) = rrA;
            *(float2*)(out + (size_t)mB*NOUT + o) = rrB;
        }
    }
}

// ---------------------------------------------------------------------------
extern "C" void kernel_launch(void* const* d_in, const int* in_sizes, int n_in,
                              void* d_out, int out_size)
{
    const float* M     = (const float*)d_in[0];
    const float* mask  = (const float*)d_in[1];
    const float* Zraw  = (const float*)d_in[2];
    const float* gamma = (const float*)d_in[3];
    const float* beta  = (const float*)d_in[4];
    const float* Wa    = (const float*)d_in[5];
    const float* ba    = (const float*)d_in[6];
    const float* Wb    = (const float*)d_in[7];
    const float* bb    = (const float*)d_in[8];
    const float* Wo    = (const float*)d_in[9];
    const float* bo    = (const float*)d_in[10];
    float* out = (float*)d_out;

    // lazily-created side stream + events (host-side objects, created on the
    // first uncaptured correctness call; reused untouched during capture)
    static cudaStream_t s2 = nullptr;
    static cudaEvent_t  evFork = nullptr, evJoin = nullptr;
    if (!s2){
        cudaStreamCreateWithFlags(&s2, cudaStreamNonBlocking);
        cudaEventCreateWithFlags(&evFork, cudaEventDisableTiming);
        cudaEventCreateWithFlags(&evJoin, cudaEventDisableTiming);
    }

    cudaFuncSetAttribute(prep_kernel,  cudaFuncAttributeMaxDynamicSharedMemorySize, PREP_SMEM);
    cudaFuncSetAttribute(gemm1_kernel, cudaFuncAttributeMaxDynamicSharedMemorySize, G1_SMEM);
    cudaFuncSetAttribute(gemm2_kernel, cudaFuncAttributeMaxDynamicSharedMemorySize, G2_SMEM);

    // fork: norm (+wconv) runs on s2 concurrently with prep+gemm1
    cudaEventRecord(evFork, 0);
    cudaStreamWaitEvent(s2, evFork, 0);
    norm_kernel<<<dim3(12,12), 256, 0, s2>>>(mask, Wo);
    cudaEventRecord(evJoin, s2);

    prep_kernel<<<NRES, 256, PREP_SMEM>>>(M, mask, gamma, beta, Wa, ba, Wb, bb);
    gemm1_kernel<<<dim3(96, 96), 128, G1_SMEM>>>();

    // join: gemm2 needs g_normv + g_Wob from s2
    cudaStreamWaitEvent(0, evJoin, 0);
    gemm2_kernel<<<NPAIR/128, 128, G2_SMEM>>>(Zraw, bo, out);
}